// round 2
// baseline (speedup 1.0000x reference)
#include <cuda_runtime.h>
#include <math.h>

#define NEGV -1e30f
#define FS 580   // feed row stride (575 supersteps + prefetch pad)

// ---- static device scratch ----
__device__ float g_S[4 * 512 * 512];        // plain score matrices
__device__ float g_n2[2 * 4 * 512];         // row norms
__device__ float g_Sf[4 * 8 * FS * 64];     // skewed S feed  [b][c][u][t]
__device__ float g_gof[8 * FS * 64];        // skewed go feed [c][u][t]
__device__ float g_gef[8 * FS * 64];        // skewed ge feed
__device__ float g_Df[4 * 8 * FS * 64];     // skewed D output feed
__device__ float4 g_bnd[4 * 8 * 516];       // chunk-boundary ring {D,Ix,h,k} per row
__device__ int   g_flag[32];                // progress flags [b*8+c]
__device__ float g_pm[288], g_ps[288];      // LSE partials

__device__ __forceinline__ float lse2(float a, float b) {
    float m = fmaxf(a, b);
    float n = fminf(a, b);
    return m + __logf(1.0f + __expf(n - m));
}

// ================= norms + flag reset =================
__global__ void norm_kernel(const float* __restrict__ x, const float* __restrict__ y) {
    if (blockIdx.x == 0 && threadIdx.x < 32) g_flag[threadIdx.x] = 0;
    int w = (blockIdx.x * blockDim.x + threadIdx.x) >> 5;
    int lane = threadIdx.x & 31;
    #pragma unroll
    for (int s = 0; s < 16; s++) {
        int row = w + s * 256;
        const float* p = (row < 2048) ? (x + row * 128) : (y + (row - 2048) * 128);
        float v0 = p[lane], v1 = p[lane + 32], v2 = p[lane + 64], v3 = p[lane + 96];
        float sum = v0 * v0 + v1 * v1 + v2 * v2 + v3 * v3;
        #pragma unroll
        for (int o = 16; o > 0; o >>= 1) sum += __shfl_xor_sync(0xffffffffu, sum, o);
        if (lane == 0) g_n2[row] = sum;
    }
}

// ================= S = x2 + y2 - 2 x.y  (64x64 tiles) =================
__global__ void __launch_bounds__(256) dist_kernel(const float* __restrict__ x,
                                                   const float* __restrict__ y) {
    int b = blockIdx.z;
    int i0 = blockIdx.y * 64, j0 = blockIdx.x * 64;
    const float* xb = x + (b * 512 + i0) * 128;
    const float* yb = y + (b * 512 + j0) * 128;
    __shared__ float xs[16][64];
    __shared__ float ys[16][64];
    int tid = threadIdx.x;
    int tx = tid & 15, ty = tid >> 4;
    float acc[4][4];
    #pragma unroll
    for (int r = 0; r < 4; r++)
        #pragma unroll
        for (int c = 0; c < 4; c++) acc[r][c] = 0.f;

    for (int kc = 0; kc < 128; kc += 16) {
        __syncthreads();
        #pragma unroll
        for (int l = 0; l < 4; l++) {
            int e = tid + l * 256;
            int r = e >> 4, kk = e & 15;
            xs[kk][r] = xb[r * 128 + kc + kk];
            ys[kk][r] = yb[r * 128 + kc + kk];
        }
        __syncthreads();
        #pragma unroll
        for (int kk = 0; kk < 16; kk++) {
            float4 a  = *(const float4*)&xs[kk][ty * 4];
            float4 bv = *(const float4*)&ys[kk][tx * 4];
            float ar[4] = {a.x, a.y, a.z, a.w};
            float br[4] = {bv.x, bv.y, bv.z, bv.w};
            #pragma unroll
            for (int r = 0; r < 4; r++)
                #pragma unroll
                for (int c = 0; c < 4; c++)
                    acc[r][c] = fmaf(ar[r], br[c], acc[r][c]);
        }
    }
    float x2[4], y2[4];
    #pragma unroll
    for (int r = 0; r < 4; r++) x2[r] = g_n2[b * 512 + i0 + ty * 4 + r];
    #pragma unroll
    for (int c = 0; c < 4; c++) y2[c] = g_n2[2048 + b * 512 + j0 + tx * 4 + c];
    float* Sb = g_S + b * 262144;
    #pragma unroll
    for (int r = 0; r < 4; r++) {
        float4 o;
        o.x = x2[r] + y2[0] - 2.f * acc[r][0];
        o.y = x2[r] + y2[1] - 2.f * acc[r][1];
        o.z = x2[r] + y2[2] - 2.f * acc[r][2];
        o.w = x2[r] + y2[3] - 2.f * acc[r][3];
        *(float4*)&Sb[(i0 + ty * 4 + r) * 512 + j0 + tx * 4] = o;
    }
}

// ================= reskew: matrix [512][512] -> feed [c][u][t] =================
// feed[c][u][t] = M[u - t][c*64 + t]   (row index i-1 = u - t)
__global__ void __launch_bounds__(256) reskew_kernel(const float* __restrict__ go,
                                                     const float* __restrict__ ge) {
    int m = blockIdx.y;                 // 0..3 = S batches, 4 = go, 5 = ge
    int c = blockIdx.x / 9, ub = blockIdx.x % 9;
    const float* src = (m < 4) ? (g_S + m * 262144) : ((m == 4) ? go : ge);
    float* dst = (m < 4) ? (g_Sf + m * (8 * FS * 64)) : ((m == 4) ? g_gof : g_gef);
    __shared__ float sm[128 * 64];
    int tid = threadIdx.x;
    int u0 = ub * 64;
    #pragma unroll
    for (int l = 0; l < 32; l++) {
        int e = tid + l * 256;
        int r = e >> 6, col = e & 63;
        int gi = u0 - 63 + r;
        sm[e] = (gi >= 0 && gi < 512) ? src[gi * 512 + c * 64 + col] : 0.f;
    }
    __syncthreads();
    #pragma unroll
    for (int l = 0; l < 16; l++) {
        int e = tid + l * 256;
        int ur = e >> 6, t = e & 63;
        dst[(c * FS + u0 + ur) * 64 + t] = sm[(ur + 63 - t) * 64 + t];
    }
}

// ================= wavefront soft-SW; 8 chunk-CTAs per batch =================
__global__ void __launch_bounds__(64) sw_kernel() {
    const int c = blockIdx.x, b = blockIdx.y;
    const int t = threadIdx.x, lane = t & 31, warp = t >> 5;
    const float* Sf  = g_Sf + (b * 8 + c) * (FS * 64);
    const float* gof = g_gof + c * (FS * 64);
    const float* gef = g_gef + c * (FS * 64);
    float* Df = g_Df + (b * 8 + c) * (FS * 64);
    float4* bndW = g_bnd + (b * 8 + c) * 516;
    const float4* bndR = g_bnd + (b * 8 + c - 1) * 516;
    int* flagW = &g_flag[b * 8 + c];
    int* flagR = &g_flag[b * 8 + c - 1];

    __shared__ float sh[2][2][4];   // [parity][warp][D,Ix,h,k]
    if (t < 16) ((float*)sh)[t] = ((t & 3) == 3) ? 0.f : NEGV;

    float D = NEGV, Ix = NEGV, Iy = NEGV, h = NEGV, k = 0.f;
    float hs = NEGV, ks = 0.f;      // stale left h,k (diag deps)

    float4 cur = make_float4(NEGV, NEGV, NEGV, 0.f);
    float4 nxt = cur;
    int avail = 0;
    if (t == 0 && c > 0) {
        while (avail < 2)
            asm volatile("ld.acquire.gpu.s32 %0, [%1];" : "=r"(avail) : "l"(flagR) : "memory");
        cur = bndR[1];
        nxt = bndR[2];
    }

    float sC = Sf[t],       sN = Sf[64 + t];
    float goC = gof[t],     goN = gof[64 + t];
    float geC = gef[t],     geN = gef[64 + t];
    __syncthreads();

    for (int u = 0; u < 575; u++) {
        // prefetch feed for u+2
        int pidx = (u + 2) * 64 + t;
        float sT = Sf[pidx], goT = gof[pidx], geT = gef[pidx];
        float4 bT = nxt;
        if (t == 0 && c > 0) {
            int r = u + 3;
            if (r <= 512) {
                if (avail < r) {
                    do {
                        asm volatile("ld.acquire.gpu.s32 %0, [%1];" : "=r"(avail) : "l"(flagR) : "memory");
                    } while (avail < r);
                }
                bT = bndR[r];
            }
        }
        // neighbor fresh values (results of superstep u-1)
        float nD  = __shfl_up_sync(0xffffffffu, D, 1);
        float nIx = __shfl_up_sync(0xffffffffu, Ix, 1);
        float nh  = __shfl_up_sync(0xffffffffu, h, 1);
        float nk  = __shfl_up_sync(0xffffffffu, k, 1);
        if (lane == 0) {
            if (warp == 1) {
                int p = (u + 1) & 1;
                nD = sh[p][0][0]; nIx = sh[p][0][1]; nh = sh[p][0][2]; nk = sh[p][0][3];
            } else if (c == 0) {
                nD = NEGV; nIx = NEGV; nh = NEGV; nk = 0.f;
            } else {
                nD = cur.x; nIx = cur.y; nh = cur.z; nk = cur.w;
            }
        }
        bool act = (u >= t) && (u - t < 512);
        if (act) {
            float ix = lse2(nD - goC, nIx - geC);     // left deps (fresh)
            float iy = lse2(h - goC, Iy - geC);       // up deps (own prev row)
            float d  = sC + lse2(hs, ks);             // diag deps (stale)
            D = d; Ix = ix; Iy = iy;
            h = lse2(d, ix);
            k = lse2(iy, 0.f);
            Df[u * 64 + t] = d;
            if (t == 63 && c < 7) {
                int i = u - 62;
                bndW[i] = make_float4(d, ix, h, k);
                if ((i & 15) == 0 || i == 512)
                    asm volatile("st.release.gpu.s32 [%0], %1;" :: "l"(flagW), "r"(i) : "memory");
            }
        }
        hs = nh; ks = nk;
        if (lane == 31) {
            sh[u & 1][warp][0] = D;  sh[u & 1][warp][1] = Ix;
            sh[u & 1][warp][2] = h;  sh[u & 1][warp][3] = k;
        }
        sC = sN; sN = sT;
        goC = goN; goN = goT;
        geC = geN; geN = geT;
        cur = nxt; nxt = bT;
        __syncthreads();
    }
}

// ================= LSE over valid D entries (skewed feed) =================
__global__ void lse_part() {
    int bx = blockIdx.x;          // 0..71 : chunk*9 + ublock
    int b = blockIdx.y;
    int cchunk = bx / 9, ub = bx % 9;
    const float* Df = g_Df + (b * 8 + cchunk) * (FS * 64) + ub * 64 * 64;
    int tid = threadIdx.x;
    float m = NEGV, s = 0.f;
    #pragma unroll
    for (int l = 0; l < 16; l++) {
        int e = tid + l * 256;
        int ur = e >> 6, t = e & 63;
        int u = ub * 64 + ur;
        bool valid = (u >= t) && (u - t < 512);
        float d = valid ? Df[e] : NEGV;
        float nm = fmaxf(m, d);
        s = s * __expf(m - nm) + __expf(d - nm);
        m = nm;
    }
    __shared__ float sm[256], ss[256];
    sm[tid] = m; ss[tid] = s;
    __syncthreads();
    for (int o = 128; o > 0; o >>= 1) {
        if (tid < o) {
            float m2 = sm[tid + o], s2 = ss[tid + o];
            float nm = fmaxf(sm[tid], m2);
            ss[tid] = ss[tid] * __expf(sm[tid] - nm) + s2 * __expf(m2 - nm);
            sm[tid] = nm;
        }
        __syncthreads();
    }
    if (tid == 0) { g_pm[b * 72 + bx] = sm[0]; g_ps[b * 72 + bx] = ss[0]; }
}

__global__ void lse_final(float* __restrict__ out) {
    int t = threadIdx.x;          // 256
    int b = t >> 6, r = t & 63;
    float m = g_pm[b * 72 + r], s = g_ps[b * 72 + r];
    if (r < 8) {
        float m2 = g_pm[b * 72 + r + 64], s2 = g_ps[b * 72 + r + 64];
        float nm = fmaxf(m, m2);
        s = s * __expf(m - nm) + s2 * __expf(m2 - nm);
        m = nm;
    }
    __shared__ float sm[256], ss[256], vv[4];
    sm[t] = m; ss[t] = s;
    __syncthreads();
    for (int o = 32; o > 0; o >>= 1) {
        if (r < o) {
            float m2 = sm[t + o], s2 = ss[t + o];
            float nm = fmaxf(sm[t], m2);
            ss[t] = ss[t] * __expf(sm[t] - nm) + s2 * __expf(m2 - nm);
            sm[t] = nm;
        }
        __syncthreads();
    }
    if (r == 0) vv[b] = sm[t] + logf(ss[t]);
    __syncthreads();
    if (t == 0) out[0] = 0.25f * (vv[0] + vv[1] + vv[2] + vv[3]);
}

// ================= deskew D feed -> probas =================
__global__ void __launch_bounds__(256) deskew_kernel(float* __restrict__ out) {
    int c = blockIdx.x, rb = blockIdx.y, b = blockIdx.z;
    const float* Df = g_Df + (b * 8 + c) * (FS * 64);
    __shared__ float sm[128 * 64];
    int tid = threadIdx.x;
    int r0 = rb * 64;
    #pragma unroll
    for (int l = 0; l < 32; l++) {
        int e = tid + l * 256;
        sm[e] = Df[(r0 + (e >> 6)) * 64 + (e & 63)];
    }
    __syncthreads();
    float* ob = out + 1 + b * 262144;
    #pragma unroll
    for (int l = 0; l < 16; l++) {
        int e = tid + l * 256;
        int r = e >> 6, t = e & 63;
        ob[(r0 + r) * 512 + c * 64 + t] = sm[(r + t) * 64 + t];
    }
}

// ================= launcher =================
extern "C" void kernel_launch(void* const* d_in, const int* in_sizes, int n_in,
                              void* d_out, int out_size) {
    const float* x  = (const float*)d_in[0];
    const float* y  = (const float*)d_in[1];
    const float* go = (const float*)d_in[2];
    const float* ge = (const float*)d_in[3];
    float* out = (float*)d_out;

    norm_kernel<<<32, 256>>>(x, y);
    dist_kernel<<<dim3(8, 8, 4), 256>>>(x, y);
    reskew_kernel<<<dim3(72, 6), 256>>>(go, ge);
    sw_kernel<<<dim3(8, 4), 64>>>();
    lse_part<<<dim3(72, 4), 256>>>();
    deskew_kernel<<<dim3(8, 8, 4), 256>>>(out);
    lse_final<<<1, 256>>>(out);
}